// round 1
// baseline (speedup 1.0000x reference)
#include <cuda_runtime.h>
#include <math.h>

// Problem constants
#define Bn   64
#define Cn   512
#define Pn   64      // H*W
#define Kn   100
#define H1n  64
#define HIDn 128
#define Ln   32
#define CLIPV 100.0f
#define REDV (-0.1f)
#define PUSHT 10000.0f

#define COLS 128     // columns per CTA (= 2 batch images x 64 positions)
#define KC   32      // C-chunk for GEMM1

// ---- dynamic shared memory layout (floats) ----
// h1 region  : [64][132]                (also reused for lt[32][132] + er/er1 arrays in stage 4)
// h2 region  : [128][132]
// misc region: 8448 floats
//   stage1: Wts[32][68] (2176) + Xs[32][132] (4224)
//   stage2: W2ts[64][132] (8448)
//   stage3: W3ts[128][34] (4352) + protos[2][32][64] (4096)
#define OFF_H1   0
#define OFF_H2   (64 * 132)                  // 8448
#define OFF_MISC (OFF_H2 + 128 * 132)        // 25344
#define SMEM_FLOATS (OFF_MISC + 8448)        // 33792 floats = 135168 bytes

__device__ float f_dev[Kn * Bn];
__device__ float f1_dev[Kn * Bn];

__global__ __launch_bounds__(256, 1)
void fused_cssr(const float* __restrict__ x,
                const float* __restrict__ W1,
                const float* __restrict__ W2,
                const float* __restrict__ W3,
                const float* __restrict__ pr0,
                const float* __restrict__ pr1,
                float* __restrict__ out)
{
    extern __shared__ float sm[];
    float* h1   = sm + OFF_H1;    // [64][132]
    float* h2   = sm + OFF_H2;    // [128][132]
    float* misc = sm + OFF_MISC;

    const int k    = blockIdx.y;
    const int tile = blockIdx.x;       // 0..31
    const int b0   = tile * 2;         // two batch images per CTA
    const int tid  = threadIdx.x;
    const int tx   = tid & 15;         // 0..15 -> 8-wide column groups
    const int ty   = tid >> 4;         // 0..15 -> row groups

    // =========== Stage 1: h1[64][128] = tanh(W1_k @ X) ===========
    {
        float a1[4][8];
        #pragma unroll
        for (int i = 0; i < 4; i++)
            #pragma unroll
            for (int j = 0; j < 8; j++) a1[i][j] = 0.f;

        float* Wts = misc;             // [32][68] transposed chunk
        float* Xs  = misc + 32 * 68;   // [32][132]
        const float* W1k = W1 + (size_t)k * H1n * Cn;

        for (int c0 = 0; c0 < Cn; c0 += KC) {
            // load W1 chunk (64 x 32) transposed into Wts[cc][o]
            #pragma unroll
            for (int pass = 0; pass < 2; pass++) {
                int idx = tid + pass * 256;          // 0..511 float4s
                int o   = idx >> 3;                  // 0..63
                int c4  = (idx & 7) * 4;             // 0..28
                float4 w = *(const float4*)(W1k + (size_t)o * Cn + c0 + c4);
                Wts[(c4 + 0) * 68 + o] = w.x;
                Wts[(c4 + 1) * 68 + o] = w.y;
                Wts[(c4 + 2) * 68 + o] = w.z;
                Wts[(c4 + 3) * 68 + o] = w.w;
            }
            // load X chunk (32 x 128): col j -> (b = b0 + j/64, p = j%64)
            #pragma unroll
            for (int pass = 0; pass < 4; pass++) {
                int idx = tid + pass * 256;          // 0..1023 float4s
                int cc  = idx >> 5;                  // 0..31
                int j4  = (idx & 31) * 4;            // 0..124
                int b   = b0 + (j4 >> 6);
                int p   = j4 & 63;
                float4 v = *(const float4*)(x + ((size_t)b * Cn + (c0 + cc)) * Pn + p);
                *(float4*)(Xs + cc * 132 + j4) = v;
            }
            __syncthreads();
            #pragma unroll
            for (int cc = 0; cc < KC; cc++) {
                float4 av  = *(float4*)(Wts + cc * 68 + ty * 4);
                float4 bv0 = *(float4*)(Xs + cc * 132 + tx * 8);
                float4 bv1 = *(float4*)(Xs + cc * 132 + tx * 8 + 4);
                float as[4] = {av.x, av.y, av.z, av.w};
                float bs[8] = {bv0.x, bv0.y, bv0.z, bv0.w, bv1.x, bv1.y, bv1.z, bv1.w};
                #pragma unroll
                for (int i = 0; i < 4; i++)
                    #pragma unroll
                    for (int j = 0; j < 8; j++) a1[i][j] += as[i] * bs[j];
            }
            __syncthreads();
        }
        // tanh + store h1
        #pragma unroll
        for (int i = 0; i < 4; i++) {
            #pragma unroll
            for (int j = 0; j < 8; j++) a1[i][j] = tanhf(a1[i][j]);
            float4 v0 = make_float4(a1[i][0], a1[i][1], a1[i][2], a1[i][3]);
            float4 v1 = make_float4(a1[i][4], a1[i][5], a1[i][6], a1[i][7]);
            *(float4*)(h1 + (ty * 4 + i) * 132 + tx * 8)     = v0;
            *(float4*)(h1 + (ty * 4 + i) * 132 + tx * 8 + 4) = v1;
        }
    }
    __syncthreads();

    // =========== Stage 2: h2[128][128] = tanh(W2_k @ h1) ===========
    {
        float* W2ts = misc;            // [64][132] transposed
        const float* W2k = W2 + (size_t)k * HIDn * H1n;
        #pragma unroll
        for (int pass = 0; pass < 8; pass++) {
            int idx = tid + pass * 256;   // 0..2047 float4s
            int o   = idx >> 4;           // 0..127
            int i4  = (idx & 15) * 4;     // 0..60
            float4 w = *(const float4*)(W2k + (size_t)o * H1n + i4);
            W2ts[(i4 + 0) * 132 + o] = w.x;
            W2ts[(i4 + 1) * 132 + o] = w.y;
            W2ts[(i4 + 2) * 132 + o] = w.z;
            W2ts[(i4 + 3) * 132 + o] = w.w;
        }
        __syncthreads();

        float a2[8][8];
        #pragma unroll
        for (int i = 0; i < 8; i++)
            #pragma unroll
            for (int j = 0; j < 8; j++) a2[i][j] = 0.f;

        #pragma unroll 4
        for (int i = 0; i < H1n; i++) {
            float4 av0 = *(float4*)(W2ts + i * 132 + ty * 8);
            float4 av1 = *(float4*)(W2ts + i * 132 + ty * 8 + 4);
            float4 bv0 = *(float4*)(h1 + i * 132 + tx * 8);
            float4 bv1 = *(float4*)(h1 + i * 132 + tx * 8 + 4);
            float as[8] = {av0.x, av0.y, av0.z, av0.w, av1.x, av1.y, av1.z, av1.w};
            float bs[8] = {bv0.x, bv0.y, bv0.z, bv0.w, bv1.x, bv1.y, bv1.z, bv1.w};
            #pragma unroll
            for (int r = 0; r < 8; r++)
                #pragma unroll
                for (int c = 0; c < 8; c++) a2[r][c] += as[r] * bs[c];
        }
        // tanh + store h2
        #pragma unroll
        for (int r = 0; r < 8; r++) {
            #pragma unroll
            for (int c = 0; c < 8; c++) a2[r][c] = tanhf(a2[r][c]);
            float4 v0 = make_float4(a2[r][0], a2[r][1], a2[r][2], a2[r][3]);
            float4 v1 = make_float4(a2[r][4], a2[r][5], a2[r][6], a2[r][7]);
            *(float4*)(h2 + (ty * 8 + r) * 132 + tx * 8)     = v0;
            *(float4*)(h2 + (ty * 8 + r) * 132 + tx * 8 + 4) = v1;
        }
    }
    __syncthreads();

    // =========== Stage 3: lt[32][128] = tanh(W3_k @ h2) ===========
    {
        float* W3ts = misc;              // [128][34] transposed
        float* ps   = misc + 128 * 34;   // [2][32][64] prototypes
        const float* W3k = W3 + (size_t)k * Ln * HIDn;
        #pragma unroll
        for (int pass = 0; pass < 4; pass++) {
            int idx = tid + pass * 256;   // 0..1023 float4s
            int l   = idx >> 5;           // 0..31
            int i4  = (idx & 31) * 4;     // 0..124
            float4 w = *(const float4*)(W3k + (size_t)l * HIDn + i4);
            W3ts[(i4 + 0) * 34 + l] = w.x;
            W3ts[(i4 + 1) * 34 + l] = w.y;
            W3ts[(i4 + 2) * 34 + l] = w.z;
            W3ts[(i4 + 3) * 34 + l] = w.w;
        }
        const float* p0k = pr0 + (size_t)k * Ln * Pn;
        const float* p1k = pr1 + (size_t)k * Ln * Pn;
        #pragma unroll
        for (int pass = 0; pass < 2; pass++) {
            int idx = tid + pass * 256;   // 0..511 float4s per proto
            int e4  = idx * 4;
            *(float4*)(ps + e4)        = *(const float4*)(p0k + e4);
            *(float4*)(ps + 2048 + e4) = *(const float4*)(p1k + e4);
        }
        __syncthreads();

        float a3[2][8];
        #pragma unroll
        for (int i = 0; i < 2; i++)
            #pragma unroll
            for (int j = 0; j < 8; j++) a3[i][j] = 0.f;

        #pragma unroll 4
        for (int i = 0; i < HIDn; i++) {
            float a0  = W3ts[i * 34 + ty * 2];
            float a1v = W3ts[i * 34 + ty * 2 + 1];
            float4 bv0 = *(float4*)(h2 + i * 132 + tx * 8);
            float4 bv1 = *(float4*)(h2 + i * 132 + tx * 8 + 4);
            float bs[8] = {bv0.x, bv0.y, bv0.z, bv0.w, bv1.x, bv1.y, bv1.z, bv1.w};
            #pragma unroll
            for (int c = 0; c < 8; c++) {
                a3[0][c] += a0  * bs[c];
                a3[1][c] += a1v * bs[c];
            }
        }
        // tanh + store lt into (retired) h1 region
        float* lt = h1;
        #pragma unroll
        for (int r = 0; r < 2; r++) {
            #pragma unroll
            for (int c = 0; c < 8; c++) a3[r][c] = tanhf(a3[r][c]);
            float4 v0 = make_float4(a3[r][0], a3[r][1], a3[r][2], a3[r][3]);
            float4 v1 = make_float4(a3[r][4], a3[r][5], a3[r][6], a3[r][7]);
            *(float4*)(lt + (ty * 2 + r) * 132 + tx * 8)     = v0;
            *(float4*)(lt + (ty * 2 + r) * 132 + tx * 8 + 4) = v1;
        }
    }
    __syncthreads();

    // =========== Stage 4: distances, er/er1, per-(k,b) sums ===========
    {
        float* lt   = h1;
        float* ps   = misc + 128 * 34;
        float* ers  = h1 + 32 * 132;     // [128]
        float* er1s = ers + 128;         // [128]

        if (tid < COLS) {
            int j = tid;
            int b = b0 + (j >> 6);
            int p = j & 63;
            float d0 = 0.f, d1 = 0.f;
            #pragma unroll
            for (int l = 0; l < Ln; l++) {
                float v  = lt[l * 132 + j];
                float t0 = v - ps[l * 64 + p];
                float t1 = v - ps[2048 + l * 64 + p];
                d0 += t0 * t0;
                d1 += t1 * t1;
            }
            float er  = fminf(fmaxf(d0 * REDV, -CLIPV), CLIPV);
            float er1 = fminf(fmaxf(d1 * REDV, -CLIPV), CLIPV);
            // logits layout: [B, K, P]
            out[((size_t)b * Kn + k) * Pn + p] = er;
            out[(size_t)Bn * Kn * Pn + ((size_t)b * Kn + k) * Pn + p] = er1;
            ers[j]  = er;
            er1s[j] = er1;
        }
        __syncthreads();
        if (tid < 4) {
            int bb = tid & 1;
            const float* src = (tid < 2) ? ers : er1s;
            float s = 0.f;
            for (int p = 0; p < 64; p++) s += src[bb * 64 + p];
            if (tid < 2) f_dev[k * Bn + b0 + bb]  = s;
            else         f1_dev[k * Bn + b0 + bb] = s;
        }
    }
}

__global__ void finalize_kernel(const int* __restrict__ ycls, float* __restrict__ out)
{
    __shared__ float s_pull[128];
    __shared__ float s_push[128];
    int k = threadIdx.x;
    float pull = 0.f, push = 0.f;
    if (k < Kn) {
        float se = 0.f, sc = 0.f;
        int ne = 0, nc = 0;
        for (int b = 0; b < Bn; b++) {
            float fv  = f_dev[k * Bn + b];
            float f1v = f1_dev[k * Bn + b];
            if (ycls[b] == k) { se += f1v; ne++; }
            else if (fv < PUSHT) { sc += fv; nc++; }
        }
        if (ne > 0) pull = se / (float)ne;
        if (nc > 0) push = sc / (float)nc;
    }
    s_pull[k] = pull;
    s_push[k] = push;
    __syncthreads();
    for (int s = 64; s > 0; s >>= 1) {
        if (k < s) { s_pull[k] += s_pull[k + s]; s_push[k] += s_push[k + s]; }
        __syncthreads();
    }
    if (k == 0) {
        size_t base = (size_t)2 * Bn * Kn * Pn;
        out[base]     = s_pull[0];
        out[base + 1] = s_push[0];
    }
}

extern "C" void kernel_launch(void* const* d_in, const int* in_sizes, int n_in,
                              void* d_out, int out_size)
{
    const float* x    = (const float*)d_in[0];
    const int*   ycls = (const int*)  d_in[1];
    // d_in[2], d_in[3]: safe_margin_all / safe_distance_all — unused by reference
    const float* W1   = (const float*)d_in[4];
    const float* W2   = (const float*)d_in[5];
    const float* W3   = (const float*)d_in[6];
    const float* pr0  = (const float*)d_in[7];
    const float* pr1  = (const float*)d_in[8];
    float* out = (float*)d_out;

    size_t smem = SMEM_FLOATS * sizeof(float);
    cudaFuncSetAttribute(fused_cssr, cudaFuncAttributeMaxDynamicSharedMemorySize, (int)smem);

    dim3 grid(Pn * Bn / COLS, Kn);   // (32, 100)
    fused_cssr<<<grid, 256, smem>>>(x, W1, W2, W3, pr0, pr1, out);
    finalize_kernel<<<1, 128>>>(ycls, out);
}